// round 15
// baseline (speedup 1.0000x reference)
#include <cuda_runtime.h>
#include <cuda_fp16.h>
#include <cstdint>

#define IN_CH 50
#define OUT_CH 121
#define YPITCH 128
#define MAX_N 100000
#define MAX_E 1600000

// Node-level Y = X @ W1 stored as fp16 (25.6MB -> L2-resident)
__device__ __align__(16) __half g_y[MAX_N * YPITCH];
// Materialized H = relu((1+eps)Y[r] + Y[c] + b1), fp16 [E][128]
__device__ __align__(16) __half g_h[(size_t)MAX_E * YPITCH];

// ---------------------------------------------------------------------------
// helpers
// ---------------------------------------------------------------------------
__device__ __forceinline__ uint32_t smem_u32(const void* p) {
    uint32_t a;
    asm("{ .reg .u64 t; cvta.to.shared.u64 t, %1; cvt.u32.u64 %0, t; }" : "=r"(a) : "l"(p));
    return a;
}

#define LDSM_X4(r0, r1, r2, r3, a) \
    asm volatile("ldmatrix.sync.aligned.m8n8.x4.shared.b16 {%0,%1,%2,%3}, [%4];" \
                 : "=r"(r0), "=r"(r1), "=r"(r2), "=r"(r3) : "r"(a))

#define CP_ASYNC16(dst, src) \
    asm volatile("cp.async.cg.shared.global [%0], [%1], 16;" :: "r"(dst), "l"(src) : "memory")
#define CP_COMMIT() asm volatile("cp.async.commit_group;" ::: "memory")
#define CP_WAIT0()  asm volatile("cp.async.wait_group 0;" ::: "memory")

__device__ __forceinline__ void mma16816(float* c, const uint32_t* a, uint32_t b0, uint32_t b1) {
    asm volatile(
        "mma.sync.aligned.m16n8k16.row.col.f32.f16.f16.f32 "
        "{%0,%1,%2,%3}, {%4,%5,%6,%7}, {%8,%9}, {%0,%1,%2,%3};"
        : "+f"(c[0]), "+f"(c[1]), "+f"(c[2]), "+f"(c[3])
        : "r"(a[0]), "r"(a[1]), "r"(a[2]), "r"(a[3]), "r"(b0), "r"(b1));
}

// FFMA2 helpers (node kernel)
__device__ __forceinline__ void fma2(unsigned long long &d, unsigned long long a, unsigned long long b) {
    asm("fma.rn.f32x2 %0, %1, %2, %0;" : "+l"(d) : "l"(a), "l"(b));
}
__device__ __forceinline__ unsigned long long pack2(float x, float y) {
    unsigned long long r; asm("mov.b64 %0, {%1, %2};" : "=l"(r) : "f"(x), "f"(y)); return r;
}
__device__ __forceinline__ float2 unpack2(unsigned long long v) {
    float2 r; asm("mov.b64 {%0, %1}, %2;" : "=f"(r.x), "=f"(r.y) : "l"(v)); return r;
}

// ============================================================================
// Kernel A: Y[N,128] = X[N,50] @ W1[50,121] -> fp16, zero-padded cols
// ============================================================================
__global__ void __launch_bounds__(256, 1) node_gemm(const float* __restrict__ x,
                                                    const float* __restrict__ W1,
                                                    int N) {
    extern __shared__ float sm[];
    float* Xs  = sm;
    float* W1s = Xs + IN_CH * 132;

    int tid = threadIdx.x;
    int e0 = blockIdx.x * 128;

    for (int i = tid; i < 128 * IN_CH; i += 256) {
        int m = i / IN_CH, k = i - m * IN_CH;
        int node = e0 + m;
        Xs[k * 132 + m] = (node < N) ? x[(long)node * IN_CH + k] : 0.f;
    }
    for (int i = tid; i < IN_CH * 128; i += 256) {
        int k = i >> 7, n = i & 127;
        W1s[i] = (n < OUT_CH) ? W1[k * OUT_CH + n] : 0.f;
    }
    __syncthreads();

    int tx = tid & 15, ty = tid >> 4;
    unsigned long long acc[8][4];
#pragma unroll
    for (int i = 0; i < 8; i++)
#pragma unroll
        for (int j = 0; j < 4; j++) acc[i][j] = 0ULL;

    const float* ap  = Xs + ty * 8;
    const float* bp0 = W1s + tx * 4;
    const float* bp1 = W1s + 64 + tx * 4;

#pragma unroll 5
    for (int k = 0; k < IN_CH; k++) {
        float4 a0 = *(const float4*)(ap + k * 132);
        float4 a1 = *(const float4*)(ap + k * 132 + 4);
        float4 b0 = *(const float4*)(bp0 + k * 128);
        float4 b1 = *(const float4*)(bp1 + k * 128);
        unsigned long long bb0 = pack2(b0.x, b0.y);
        unsigned long long bb1 = pack2(b0.z, b0.w);
        unsigned long long bb2 = pack2(b1.x, b1.y);
        unsigned long long bb3 = pack2(b1.z, b1.w);
        float am[8] = {a0.x, a0.y, a0.z, a0.w, a1.x, a1.y, a1.z, a1.w};
#pragma unroll
        for (int i = 0; i < 8; i++) {
            unsigned long long aa = pack2(am[i], am[i]);
            fma2(acc[i][0], aa, bb0);
            fma2(acc[i][1], aa, bb1);
            fma2(acc[i][2], aa, bb2);
            fma2(acc[i][3], aa, bb3);
        }
    }

#pragma unroll
    for (int i = 0; i < 8; i++) {
        int node = e0 + ty * 8 + i;
        if (node < N) {
            float2 v0 = unpack2(acc[i][0]);
            float2 v1 = unpack2(acc[i][1]);
            float2 v2 = unpack2(acc[i][2]);
            float2 v3 = unpack2(acc[i][3]);
            __half2 h0 = __float22half2_rn(v0);
            __half2 h1 = __float22half2_rn(v1);
            __half2 h2 = __float22half2_rn(v2);
            __half2 h3 = __float22half2_rn(v3);
            __half* yrow = g_y + (long)node * YPITCH;
            *(uint2*)(yrow + tx * 4)      = make_uint2(*(uint32_t*)&h0, *(uint32_t*)&h1);
            *(uint2*)(yrow + 64 + tx * 4) = make_uint2(*(uint32_t*)&h2, *(uint32_t*)&h3);
        }
    }
}

// ============================================================================
// Kernel G: materialize H[e][0..127] = relu((1+eps)Y[r]+Y[c]+b1)  (fp16)
// 16 threads per edge, one uint4 (8 halves) each. Pure bandwidth shape:
// tiny regs -> high occupancy -> L2 gather latency fully hidden by MLP.
// fp32 combine (identical numerics to R12).
// ============================================================================
__global__ void __launch_bounds__(256) gather_h(const int* __restrict__ ei,
                                                const float* __restrict__ b1,
                                                const float* __restrict__ epsp,
                                                int E, int N) {
    __shared__ float b1s[128];
    int tid = threadIdx.x;
    if (tid < 128) b1s[tid] = (tid < OUT_CH) ? b1[tid] : 0.f;
    __syncthreads();

    long gid = (long)blockIdx.x * 256 + tid;
    long e = gid >> 4;
    int p = (int)(gid & 15);
    if (e >= E) return;

    float coef = 1.f + epsp[0];
    int r = ei[e], c = ei[E + e];
    if (r < 0) r = 0; if (r >= N) r = N - 1;
    if (c < 0) c = 0; if (c >= N) c = N - 1;

    uint4 a = *(const uint4*)(g_y + (long)r * YPITCH + p * 8);
    uint4 b = *(const uint4*)(g_y + (long)c * YPITCH + p * 8);
    const float* bb = b1s + p * 8;

    uint4 outv;
    {
        float2 fa, fb;
        __half2 t;
        fa = __half22float2(*(__half2*)&a.x); fb = __half22float2(*(__half2*)&b.x);
        t = __float22half2_rn(make_float2(fmaxf(fmaf(coef, fa.x, fb.x) + bb[0], 0.f),
                                          fmaxf(fmaf(coef, fa.y, fb.y) + bb[1], 0.f)));
        outv.x = *(uint32_t*)&t;
        fa = __half22float2(*(__half2*)&a.y); fb = __half22float2(*(__half2*)&b.y);
        t = __float22half2_rn(make_float2(fmaxf(fmaf(coef, fa.x, fb.x) + bb[2], 0.f),
                                          fmaxf(fmaf(coef, fa.y, fb.y) + bb[3], 0.f)));
        outv.y = *(uint32_t*)&t;
        fa = __half22float2(*(__half2*)&a.z); fb = __half22float2(*(__half2*)&b.z);
        t = __float22half2_rn(make_float2(fmaxf(fmaf(coef, fa.x, fb.x) + bb[4], 0.f),
                                          fmaxf(fmaf(coef, fa.y, fb.y) + bb[5], 0.f)));
        outv.z = *(uint32_t*)&t;
        fa = __half22float2(*(__half2*)&a.w); fb = __half22float2(*(__half2*)&b.w);
        t = __float22half2_rn(make_float2(fmaxf(fmaf(coef, fa.x, fb.x) + bb[6], 0.f),
                                          fmaxf(fmaf(coef, fa.y, fb.y) + bb[7], 0.f)));
        outv.w = *(uint32_t*)&t;
    }
    // streaming store: don't pollute L2 (Y must stay resident)
    __stcs((uint4*)(g_h + e * YPITCH + p * 8), outv);
}

// ============================================================================
// Kernel B: persistent dense fp16 GEMM over materialized H, 512 threads.
// 16 warps = 4 rowgroups (32 edges) x 4 col-groups (32 cols), tile = 128.
// A arrives by cp.async bulk (no per-edge latency); W2 register-resident.
// Double-buffered H tile; next-tile cp.async overlaps current MMA+epilogue.
// smem: W2 [128n][272B] @0 (34816); H tile bufs @34816 + b*34816; b2 @104448
// ============================================================================
#define PITCH 272
#define TILE_M 128
#define OFF_W2   0
#define OFF_HT   34816
#define HTBUF    34816
#define OFF_B2   (34816 + 2*34816)     /* 104448 */
#define SMEM_EDGE (OFF_B2 + 512 + 1024)

__global__ void __launch_bounds__(512, 1) edge_gemm(const float* __restrict__ W2,
                                                    const float* __restrict__ b2,
                                                    float* __restrict__ out,
                                                    int E, int T) {
    extern __shared__ char smraw[];
    char* sm = (char*)(((uintptr_t)smraw + 1023) & ~(uintptr_t)1023);
    uint32_t sb = smem_u32(sm);

    float* b2s = (float*)(sm + OFF_B2);

    int tid = threadIdx.x, wid = tid >> 5, lane = tid & 31;
    int rg = wid >> 2, ch = wid & 3;

    if (tid < 128) b2s[tid] = (tid < OUT_CH) ? b2[tid] : 0.f;
    for (int i = tid; i < 128 * 128; i += 512) {
        int n = i >> 7, k = i & 127;
        float v = (n < OUT_CH && k < OUT_CH) ? W2[k * OUT_CH + n] : 0.f;
        *(__half*)(sm + OFF_W2 + n * PITCH + k * 2) = __float2half(v);
    }
    __syncthreads();

    // preload this warp's B fragments (cols ch*32..+31, all K): 64 regs
    uint32_t b_off = (uint32_t)((8 * ((lane >> 4) & 1) + (lane & 7)) * PITCH + ((lane >> 3) & 1) * 16);
    uint32_t bfr[8][8];
    {
        uint32_t base = sb + OFF_W2 + (uint32_t)(ch * 32) * PITCH + b_off;
#pragma unroll
        for (int ks = 0; ks < 8; ks++) {
            uint32_t koff = (uint32_t)ks * 32u;
            LDSM_X4(bfr[ks][0], bfr[ks][1], bfr[ks][2], bfr[ks][3], base + koff);
            LDSM_X4(bfr[ks][4], bfr[ks][5], bfr[ks][6], bfr[ks][7], base + 16u * PITCH + koff);
        }
    }
    __syncthreads();   // everyone done with W2 fragment reads before loop

    int bid = blockIdx.x, G = gridDim.x;
    int nt_mine = (bid < T) ? (T - bid + G - 1) / G : 0;

    // cp.async tile load: 128 rows x 256B = 2048 x 16B chunks, 4 per thread
    auto load_tile = [&](int tile, int buf) {
        long e0 = (long)tile * TILE_M;
#pragma unroll
        for (int it = 0; it < 4; it++) {
            int i = tid + it * 512;
            int row = i >> 4, part = i & 15;
            uint32_t dst = sb + OFF_HT + (uint32_t)buf * HTBUF
                         + (uint32_t)row * PITCH + (uint32_t)part * 16u;
            long e = e0 + row;
            if (e < E) {
                CP_ASYNC16(dst, (const void*)(g_h + e * YPITCH + part * 8));
            } else {
                uint4 z = make_uint4(0, 0, 0, 0);
                asm volatile("st.shared.v4.b32 [%0], {%1,%2,%3,%4};"
                             :: "r"(dst), "r"(z.x), "r"(z.y), "r"(z.z), "r"(z.w) : "memory");
            }
        }
        CP_COMMIT();
    };

    uint32_t a_off = (uint32_t)(((lane & 7) + 8 * ((lane >> 3) & 1)) * PITCH + ((lane >> 4) & 1) * 16);
    int cq = (lane & 3) * 2;

    if (nt_mine > 0) {
        load_tile(bid, 0);
        CP_WAIT0();
        __syncthreads();
    }

    for (int j = 0; j < nt_mine; j++) {
        int cur = j & 1;
        int tile = bid + j * G;

        // issue next tile's bulk load (overlaps with MMA + epilogue below)
        if (j + 1 < nt_mine) load_tile(tile + G, 1 - cur);

        float acc[2][4][4];
#pragma unroll
        for (int mh = 0; mh < 2; mh++)
#pragma unroll
            for (int t = 0; t < 4; t++) {
                float2 bv = *(const float2*)(b2s + ch * 32 + t * 8 + cq);
                acc[mh][t][0] = bv.x; acc[mh][t][1] = bv.y;
                acc[mh][t][2] = bv.x; acc[mh][t][3] = bv.y;
            }
        uint32_t ah_b = sb + OFF_HT + (uint32_t)cur * HTBUF
                      + (uint32_t)rg * (32u * PITCH) + a_off;

#pragma unroll
        for (int s = 0; s < 8; s++) {
            uint32_t koff = (uint32_t)s * 32u;
            uint32_t ah0[4], ah1[4];
            LDSM_X4(ah0[0], ah0[1], ah0[2], ah0[3], ah_b + koff);
            LDSM_X4(ah1[0], ah1[1], ah1[2], ah1[3], ah_b + 16u * PITCH + koff);
            const uint32_t* bk = bfr[s];
#pragma unroll
            for (int n8 = 0; n8 < 4; n8++)
                mma16816(acc[0][n8], ah0, bk[n8 * 2], bk[n8 * 2 + 1]);
#pragma unroll
            for (int n8 = 0; n8 < 4; n8++)
                mma16816(acc[1][n8], ah1, bk[n8 * 2], bk[n8 * 2 + 1]);
        }

        // epilogue: streaming scalar stores
#pragma unroll
        for (int mh = 0; mh < 2; mh++) {
            int e0row = tile * TILE_M + rg * 32 + mh * 16 + (lane >> 2);
            int e1row = e0row + 8;
            bool v0 = e0row < E, v1 = e1row < E;
            float* o0 = out + (long)e0row * OUT_CH;
            float* o1 = out + (long)e1row * OUT_CH;
#pragma unroll
            for (int t = 0; t < 4; t++) {
                int n0 = ch * 32 + t * 8 + cq;
                if (n0 < OUT_CH) {
                    if (v0) __stcs(o0 + n0, acc[mh][t][0]);
                    if (v1) __stcs(o1 + n0, acc[mh][t][2]);
                    if (n0 + 1 < OUT_CH) {
                        if (v0) __stcs(o0 + n0 + 1, acc[mh][t][1]);
                        if (v1) __stcs(o1 + n0 + 1, acc[mh][t][3]);
                    }
                }
            }
        }

        if (j + 1 < nt_mine) CP_WAIT0();
        __syncthreads();
    }
}

extern "C" void kernel_launch(void* const* d_in, const int* in_sizes, int n_in,
                              void* d_out, int out_size) {
    const float* x   = (const float*)d_in[0];
    const int*   ei  = (const int*)d_in[1];
    const float* W1  = (const float*)d_in[2];
    const float* b1  = (const float*)d_in[3];
    const float* W2  = (const float*)d_in[4];
    const float* b2  = (const float*)d_in[5];
    const float* eps = (const float*)d_in[6];
    float* out = (float*)d_out;

    int N = in_sizes[0] / IN_CH;
    int E = in_sizes[1] / 2;
    int T = (E + TILE_M - 1) / TILE_M;

    size_t smA = (size_t)(IN_CH * 132 + IN_CH * 128) * sizeof(float);
    cudaFuncSetAttribute(node_gemm, cudaFuncAttributeMaxDynamicSharedMemorySize, (int)smA);
    cudaFuncSetAttribute(edge_gemm, cudaFuncAttributeMaxDynamicSharedMemorySize, SMEM_EDGE);

    node_gemm<<<(N + 127) / 128, 256, smA>>>(x, W1, N);

    long gthreads = (long)E * 16;
    int gblocks = (int)((gthreads + 255) / 256);
    gather_h<<<gblocks, 256>>>(ei, b1, eps, E, N);

    int grid = 148; if (grid > T) grid = T;
    edge_gemm<<<grid, 512, SMEM_EDGE>>>(W2, b2, out, E, T);
}

// round 16
// speedup vs baseline: 1.2009x; 1.2009x over previous
#include <cuda_runtime.h>
#include <cuda_fp16.h>
#include <cstdint>

#define IN_CH 50
#define OUT_CH 121
#define YPITCH 128
#define MAX_N 100000

// Node-level Y = X @ W1 stored as fp16 (25.6MB -> L2-resident)
__device__ __align__(16) __half g_y[MAX_N * YPITCH];

// ---------------------------------------------------------------------------
// helpers
// ---------------------------------------------------------------------------
__device__ __forceinline__ uint32_t smem_u32(const void* p) {
    uint32_t a;
    asm("{ .reg .u64 t; cvta.to.shared.u64 t, %1; cvt.u32.u64 %0, t; }" : "=r"(a) : "l"(p));
    return a;
}

#define LDSM_X4(r0, r1, r2, r3, a) \
    asm volatile("ldmatrix.sync.aligned.m8n8.x4.shared.b16 {%0,%1,%2,%3}, [%4];" \
                 : "=r"(r0), "=r"(r1), "=r"(r2), "=r"(r3) : "r"(a))

// rowgroup barrier: 4 warps (128 threads), ids 1..4
#define BAR_RG(id) asm volatile("bar.sync %0, 128;" :: "r"(id) : "memory")

__device__ __forceinline__ void mma16816(float* c, const uint32_t* a, uint32_t b0, uint32_t b1) {
    asm volatile(
        "mma.sync.aligned.m16n8k16.row.col.f32.f16.f16.f32 "
        "{%0,%1,%2,%3}, {%4,%5,%6,%7}, {%8,%9}, {%0,%1,%2,%3};"
        : "+f"(c[0]), "+f"(c[1]), "+f"(c[2]), "+f"(c[3])
        : "r"(a[0]), "r"(a[1]), "r"(a[2]), "r"(a[3]), "r"(b0), "r"(b1));
}

// FFMA2 helpers (node kernel)
__device__ __forceinline__ void fma2(unsigned long long &d, unsigned long long a, unsigned long long b) {
    asm("fma.rn.f32x2 %0, %1, %2, %0;" : "+l"(d) : "l"(a), "l"(b));
}
__device__ __forceinline__ unsigned long long pack2(float x, float y) {
    unsigned long long r; asm("mov.b64 %0, {%1, %2};" : "=l"(r) : "f"(x), "f"(y)); return r;
}
__device__ __forceinline__ float2 unpack2(unsigned long long v) {
    float2 r; asm("mov.b64 {%0, %1}, %2;" : "=f"(r.x), "=f"(r.y) : "l"(v)); return r;
}

// ============================================================================
// Kernel A: Y[N,128] = X[N,50] @ W1[50,121] -> fp16, zero-padded cols
// ============================================================================
__global__ void __launch_bounds__(256, 1) node_gemm(const float* __restrict__ x,
                                                    const float* __restrict__ W1,
                                                    int N) {
    extern __shared__ float sm[];
    float* Xs  = sm;
    float* W1s = Xs + IN_CH * 132;

    int tid = threadIdx.x;
    int e0 = blockIdx.x * 128;

    for (int i = tid; i < 128 * IN_CH; i += 256) {
        int m = i / IN_CH, k = i - m * IN_CH;
        int node = e0 + m;
        Xs[k * 132 + m] = (node < N) ? x[(long)node * IN_CH + k] : 0.f;
    }
    for (int i = tid; i < IN_CH * 128; i += 256) {
        int k = i >> 7, n = i & 127;
        W1s[i] = (n < OUT_CH) ? W1[k * OUT_CH + n] : 0.f;
    }
    __syncthreads();

    int tx = tid & 15, ty = tid >> 4;
    unsigned long long acc[8][4];
#pragma unroll
    for (int i = 0; i < 8; i++)
#pragma unroll
        for (int j = 0; j < 4; j++) acc[i][j] = 0ULL;

    const float* ap  = Xs + ty * 8;
    const float* bp0 = W1s + tx * 4;
    const float* bp1 = W1s + 64 + tx * 4;

#pragma unroll 5
    for (int k = 0; k < IN_CH; k++) {
        float4 a0 = *(const float4*)(ap + k * 132);
        float4 a1 = *(const float4*)(ap + k * 132 + 4);
        float4 b0 = *(const float4*)(bp0 + k * 128);
        float4 b1 = *(const float4*)(bp1 + k * 128);
        unsigned long long bb0 = pack2(b0.x, b0.y);
        unsigned long long bb1 = pack2(b0.z, b0.w);
        unsigned long long bb2 = pack2(b1.x, b1.y);
        unsigned long long bb3 = pack2(b1.z, b1.w);
        float am[8] = {a0.x, a0.y, a0.z, a0.w, a1.x, a1.y, a1.z, a1.w};
#pragma unroll
        for (int i = 0; i < 8; i++) {
            unsigned long long aa = pack2(am[i], am[i]);
            fma2(acc[i][0], aa, bb0);
            fma2(acc[i][1], aa, bb1);
            fma2(acc[i][2], aa, bb2);
            fma2(acc[i][3], aa, bb3);
        }
    }

#pragma unroll
    for (int i = 0; i < 8; i++) {
        int node = e0 + ty * 8 + i;
        if (node < N) {
            float2 v0 = unpack2(acc[i][0]);
            float2 v1 = unpack2(acc[i][1]);
            float2 v2 = unpack2(acc[i][2]);
            float2 v3 = unpack2(acc[i][3]);
            __half2 h0 = __float22half2_rn(v0);
            __half2 h1 = __float22half2_rn(v1);
            __half2 h2 = __float22half2_rn(v2);
            __half2 h3 = __float22half2_rn(v3);
            __half* yrow = g_y + (long)node * YPITCH;
            *(uint2*)(yrow + tx * 4)      = make_uint2(*(uint32_t*)&h0, *(uint32_t*)&h1);
            *(uint2*)(yrow + 64 + tx * 4) = make_uint2(*(uint32_t*)&h2, *(uint32_t*)&h3);
        }
    }
}

// ============================================================================
// Kernel B: persistent fp16 mma.sync edge GEMM, 512 threads (R12 base).
// 16 warps = 4 rowgroups (32 edges) x 4 col-groups (32 cols), tile = 128.
// Y fp16 (L2-resident), combine fp32, H fp16, W2 register-resident.
// Gather in 4 uint4 chunks (16B/lane): chunk c LDG at MMA step 2c,
// converted at step 2c+4 -> 4-step consume distance (~L2 latency) and
// half the gather LDG count / L1tex wavefronts vs uint2 chunks.
// ============================================================================
#define PITCH 272
#define TILE_M 128
#define OFF_W2   0
#define OFF_H    34816
#define RGBYTES  8704             /* 32 rows * 272 */
#define HBUF     34816            /* 4 rowgroups */
#define OFF_B1   (34816 + 2*34816)           /* 104448 */
#define OFF_B2   (OFF_B1 + 512)
#define SMEM_EDGE (OFF_B2 + 512 + 1024)

__global__ void __launch_bounds__(512, 1) edge_mma(const int* __restrict__ ei,
                                                   const float* __restrict__ b1,
                                                   const float* __restrict__ W2,
                                                   const float* __restrict__ b2,
                                                   const float* __restrict__ epsp,
                                                   float* __restrict__ out,
                                                   int E, int N, int T) {
    extern __shared__ char smraw[];
    char* sm = (char*)(((uintptr_t)smraw + 1023) & ~(uintptr_t)1023);
    uint32_t sb = smem_u32(sm);

    float* b1s = (float*)(sm + OFF_B1);
    float* b2s = (float*)(sm + OFF_B2);

    int tid = threadIdx.x, wid = tid >> 5, lane = tid & 31;
    int rg = wid >> 2, ch = wid & 3;
    int barid = rg + 1;

    // ---- one-time: W2 -> fp16, [n][k] padded rows; biases ----
    if (tid < 128) {
        b1s[tid] = (tid < OUT_CH) ? b1[tid] : 0.f;
        b2s[tid] = (tid < OUT_CH) ? b2[tid] : 0.f;
    }
    for (int i = tid; i < 128 * 128; i += 512) {
        int n = i >> 7, k = i & 127;
        float v = (n < OUT_CH && k < OUT_CH) ? W2[k * OUT_CH + n] : 0.f;
        *(__half*)(sm + OFF_W2 + n * PITCH + k * 2) = __float2half(v);
    }
    __syncthreads();

    // ---- preload this warp's B fragments (cols ch*32..+31, all K): 64 regs ----
    uint32_t b_off = (uint32_t)((8 * ((lane >> 4) & 1) + (lane & 7)) * PITCH + ((lane >> 3) & 1) * 16);
    uint32_t bfr[8][8];
    {
        uint32_t base = sb + OFF_W2 + (uint32_t)(ch * 32) * PITCH + b_off;
#pragma unroll
        for (int ks = 0; ks < 8; ks++) {
            uint32_t koff = (uint32_t)ks * 32u;
            LDSM_X4(bfr[ks][0], bfr[ks][1], bfr[ks][2], bfr[ks][3], base + koff);
            LDSM_X4(bfr[ks][4], bfr[ks][5], bfr[ks][6], bfr[ks][7], base + 16u * PITCH + koff);
        }
    }

    float coef = 1.f + epsp[0];
    int bid = blockIdx.x, G = gridDim.x;
    int nt_mine = (bid < T) ? (T - bid + G - 1) / G : 0;

    int m_local = ch * 8 + (lane >> 2);
    int m_tile  = rg * 32 + m_local;
    int kq      = (lane & 3) * 8;          // 8-half (16B) sub-chunk within a 32-half chunk
    char* Hrg_base = sm + OFF_H + rg * RGBYTES + m_local * PITCH;

    // fp32 combine of 8 halves (one uint4), write one uint4 to H smem
    auto convert8 = [&](uint4 a, uint4 b, int k, char* dh) {
        float4 bb0 = *(const float4*)(b1s + k);
        float4 bb1 = *(const float4*)(b1s + k + 4);
        float2 fa, fb;
        __half2 t0, t1, t2, t3;
        fa = __half22float2(*(__half2*)&a.x); fb = __half22float2(*(__half2*)&b.x);
        t0 = __float22half2_rn(make_float2(fmaxf(fmaf(coef, fa.x, fb.x) + bb0.x, 0.f),
                                           fmaxf(fmaf(coef, fa.y, fb.y) + bb0.y, 0.f)));
        fa = __half22float2(*(__half2*)&a.y); fb = __half22float2(*(__half2*)&b.y);
        t1 = __float22half2_rn(make_float2(fmaxf(fmaf(coef, fa.x, fb.x) + bb0.z, 0.f),
                                           fmaxf(fmaf(coef, fa.y, fb.y) + bb0.w, 0.f)));
        fa = __half22float2(*(__half2*)&a.z); fb = __half22float2(*(__half2*)&b.z);
        t2 = __float22half2_rn(make_float2(fmaxf(fmaf(coef, fa.x, fb.x) + bb1.x, 0.f),
                                           fmaxf(fmaf(coef, fa.y, fb.y) + bb1.y, 0.f)));
        fa = __half22float2(*(__half2*)&a.w); fb = __half22float2(*(__half2*)&b.w);
        t3 = __float22half2_rn(make_float2(fmaxf(fmaf(coef, fa.x, fb.x) + bb1.z, 0.f),
                                           fmaxf(fmaf(coef, fa.y, fb.y) + bb1.w, 0.f)));
        *(uint4*)(dh + k * 2) = make_uint4(*(uint32_t*)&t0, *(uint32_t*)&t1,
                                           *(uint32_t*)&t2, *(uint32_t*)&t3);
    };

    auto load_idx = [&](int tile, int &r, int &c) {
        int e = tile * TILE_M + m_tile;
        int rr = 0, cc = 0;
        if (tile < T && e < E) { rr = ei[e]; cc = ei[E + e]; }
        if (rr < 0) rr = 0; if (rr >= N) rr = N - 1;
        if (cc < 0) cc = 0; if (cc >= N) cc = N - 1;
        r = rr; c = cc;
    };

    auto gather_sync = [&](int tile, int buf) {
        int r, c;
        load_idx(tile, r, c);
        const __half* yr = g_y + (long)r * YPITCH;
        const __half* yc = g_y + (long)c * YPITCH;
        char* dh = Hrg_base + buf * HBUF;
#pragma unroll
        for (int cI = 0; cI < 4; cI++) {
            int k = cI * 32 + kq;
            convert8(*(const uint4*)(yr + k), *(const uint4*)(yc + k), k, dh);
        }
    };

    uint32_t a_off = (uint32_t)(((lane & 7) + 8 * ((lane >> 3) & 1)) * PITCH + ((lane >> 4) & 1) * 16);
    uint32_t aA_base = sb + OFF_H + (uint32_t)rg * (uint32_t)RGBYTES + a_off;

    int cq = (lane & 3) * 2;

    int rn = 0, cn = 0;   // indices for tile j+1
    if (nt_mine > 0) {
        gather_sync(bid, 0);
        load_idx(bid + G, rn, cn);
        BAR_RG(barid);
    }

    for (int j = 0; j < nt_mine; j++) {
        int cur = j & 1;
        int tile = bid + j * G;
        bool gon = (j + 1 < nt_mine);

        const __half* yr = g_y + (long)rn * YPITCH;
        const __half* yc = g_y + (long)cn * YPITCH;
        load_idx(tile + 2 * G, rn, cn);

        char* dh = Hrg_base + (1 - cur) * HBUF;

        float acc[2][4][4];
#pragma unroll
        for (int mh = 0; mh < 2; mh++)
#pragma unroll
            for (int t = 0; t < 4; t++) {
                float2 bv = *(const float2*)(b2s + ch * 32 + t * 8 + cq);
                acc[mh][t][0] = bv.x; acc[mh][t][1] = bv.y;
                acc[mh][t][2] = bv.x; acc[mh][t][3] = bv.y;
            }
        uint32_t ah_b = aA_base + (uint32_t)cur * (uint32_t)HBUF;

        uint4 ya[2], yb[2];   // 2 uint4 chunk slots (4-step consume distance)

#pragma unroll
        for (int s = 0; s < 8; s++) {
            if (gon) {
                if (s >= 4 && (s & 1) == 0) {
                    // convert chunk (s-4)/2 (its LDG has 4 MMA-steps of cover)
                    int cc = (s - 4) >> 1;
                    convert8(ya[cc & 1], yb[cc & 1], cc * 32 + kq, dh);
                }
                if ((s & 1) == 0) {
                    // load chunk s/2 into slot (s/2)&1 (after convert freed it)
                    int cc = s >> 1;
                    int k = cc * 32 + kq;
                    ya[cc & 1] = *(const uint4*)(yr + k);
                    yb[cc & 1] = *(const uint4*)(yc + k);
                }
            }
            // MMA step ks = s: A from smem, B from registers
            uint32_t koff = (uint32_t)s * 32u;
            uint32_t ah0[4], ah1[4];
            LDSM_X4(ah0[0], ah0[1], ah0[2], ah0[3], ah_b + koff);
            LDSM_X4(ah1[0], ah1[1], ah1[2], ah1[3], ah_b + 16u * PITCH + koff);
            const uint32_t* bk = bfr[s];
#pragma unroll
            for (int n8 = 0; n8 < 4; n8++)
                mma16816(acc[0][n8], ah0, bk[n8 * 2], bk[n8 * 2 + 1]);
#pragma unroll
            for (int n8 = 0; n8 < 4; n8++)
                mma16816(acc[1][n8], ah1, bk[n8 * 2], bk[n8 * 2 + 1]);
        }

        // tail: convert chunk 2 (loaded step 4), then epilogue, then chunk 3
        if (gon) convert8(ya[0], yb[0], 2 * 32 + kq, dh);

        // epilogue: streaming scalar stores (evict-first: keep Y in L2)
#pragma unroll
        for (int mh = 0; mh < 2; mh++) {
            int e0row = tile * TILE_M + rg * 32 + mh * 16 + (lane >> 2);
            int e1row = e0row + 8;
            bool v0 = e0row < E, v1 = e1row < E;
            float* o0 = out + (long)e0row * OUT_CH;
            float* o1 = out + (long)e1row * OUT_CH;
#pragma unroll
            for (int t = 0; t < 4; t++) {
                int n0 = ch * 32 + t * 8 + cq;
                if (n0 < OUT_CH) {
                    if (v0) __stcs(o0 + n0, acc[mh][t][0]);
                    if (v1) __stcs(o1 + n0, acc[mh][t][2]);
                    if (n0 + 1 < OUT_CH) {
                        if (v0) __stcs(o0 + n0 + 1, acc[mh][t][1]);
                        if (v1) __stcs(o1 + n0 + 1, acc[mh][t][3]);
                    }
                }
            }
        }

        if (gon) convert8(ya[1], yb[1], 3 * 32 + kq, dh);

        BAR_RG(barid);
    }
}

extern "C" void kernel_launch(void* const* d_in, const int* in_sizes, int n_in,
                              void* d_out, int out_size) {
    const float* x   = (const float*)d_in[0];
    const int*   ei  = (const int*)d_in[1];
    const float* W1  = (const float*)d_in[2];
    const float* b1  = (const float*)d_in[3];
    const float* W2  = (const float*)d_in[4];
    const float* b2  = (const float*)d_in[5];
    const float* eps = (const float*)d_in[6];
    float* out = (float*)d_out;

    int N = in_sizes[0] / IN_CH;
    int E = in_sizes[1] / 2;
    int T = (E + TILE_M - 1) / TILE_M;

    size_t smA = (size_t)(IN_CH * 132 + IN_CH * 128) * sizeof(float);
    cudaFuncSetAttribute(node_gemm, cudaFuncAttributeMaxDynamicSharedMemorySize, (int)smA);
    cudaFuncSetAttribute(edge_mma, cudaFuncAttributeMaxDynamicSharedMemorySize, SMEM_EDGE);

    node_gemm<<<(N + 127) / 128, 256, smA>>>(x, W1, N);

    int grid = 148; if (grid > T) grid = T;
    edge_mma<<<grid, 512, SMEM_EDGE>>>(ei, b1, W2, b2, eps, out, E, N, T);
}